// round 15
// baseline (speedup 1.0000x reference)
#include <cuda_runtime.h>
#include <math.h>

// Problem constants
#define BB 2
#define CI 32
#define CO 32
#define TT 64
#define MT 32

typedef unsigned long long u64t;

// ---------- packed f32x2 helpers (Blackwell FFMA2 path, PTX-only) ----------
__device__ __forceinline__ u64t pack2(float lo, float hi) {
    u64t r; asm("mov.b64 %0, {%1, %2};" : "=l"(r) : "f"(lo), "f"(hi)); return r;
}
__device__ __forceinline__ u64t bcast2(float v) { return pack2(v, v); }
__device__ __forceinline__ void fma2(u64t& d, u64t a, u64t b) {
    asm("fma.rn.f32x2 %0, %1, %2, %3;" : "=l"(d) : "l"(a), "l"(b), "l"(d));
}
__device__ __forceinline__ float2 f2of(u64t v) {
    float lo, hi; asm("mov.b64 {%0, %1}, %2;" : "=f"(lo), "=f"(hi) : "l"(v));
    return make_float2(lo, hi);
}

// -------- scratch (static device globals; no allocation) --------
__device__ float2 g_B2[BB*CI*TT*1024];   // (b,i,t,q,p)    33.5 MB
__device__ float2 g_C [BB*CI*MT*1024];   // (b,i,tf,q,p)   16.8 MB
__device__ float2 g_D [BB*CO*MT*1024];   // (b,o,t,q,p)    16.8 MB  (mixed, pre-inverse-time)
__device__ float2 g_E [BB*CO*TT*1024];   // (b,o,tau,q,p)  33.5 MB

// -------- twiddle tables --------
__device__ float2 g_tFy [128*32];  // [y][p]   (c,s):  e^{-2pi i j_in(p) y/128}, j_in=(p+49)%65
__device__ float4 g_tFx4[32*128];  // [q][x]   (c,s,-s,c): e^{-2pi i kx(q) x/128}, kx=(q+112)%128
__device__ float4 g_tFt4[32*64];   // [tf][t]  (c,s,-s,c): e^{-2pi i tf t/64}
__device__ float2 g_tIt2[32*32];   // [t2][t]  (c,s)/64:   e^{+2pi i t2 t/64}   (t2<32; parity trick gives t2+32)
__device__ float4 g_tIx4[128*32];  // [x][q]   (c,s,-s,c)/128: e^{+2pi i kx(q) x/128}
__device__ float4 g_tIy4[32*64];   // [p][yg*4+jy2] (a(y0),a(y1),b(y0),b(y1)), y0=yg+32*jy2, y1=y0+16

__global__ void k_init_tables()
{
    int tid = blockIdx.x * blockDim.x + threadIdx.x;
    if (tid < 4096) {                      // tFy
        int y = tid >> 5, p = tid & 31;
        int j = (p + 49) % 65;
        int r = (j * y) & 127;
        float s, c; sincospif(-2.0f * (float)r / 128.0f, &s, &c);
        g_tFy[tid] = make_float2(c, s);
    } else if (tid < 8192) {               // tFx4
        int i = tid - 4096; int q = i >> 7, x = i & 127;
        int k = (q + 112) & 127;
        int r = (k * x) & 127;
        float s, c; sincospif(-2.0f * (float)r / 128.0f, &s, &c);
        g_tFx4[i] = make_float4(c, s, -s, c);
    } else if (tid < 10240) {              // tFt4
        int i = tid - 8192; int tf = i >> 6, t = i & 63;
        int r = (tf * t) & 63;
        float s, c; sincospif(-2.0f * (float)r / 64.0f, &s, &c);
        g_tFt4[i] = make_float4(c, s, -s, c);
    } else if (tid < 11264) {              // tIt2
        int i = tid - 10240; int t2 = i >> 5, t = i & 31;
        int r = (t2 * t) & 63;
        float s, c; sincospif(2.0f * (float)r / 64.0f, &s, &c);
        g_tIt2[i] = make_float2(c / 64.0f, s / 64.0f);
    } else if (tid < 15360) {              // tIx4
        int i = tid - 11264; int x = i >> 5, q = i & 31;
        int k = (q + 112) & 127;
        int r = (k * x) & 127;
        float s, c; sincospif(2.0f * (float)r / 128.0f, &s, &c);
        g_tIx4[i] = make_float4(c / 128.0f, s / 128.0f, -s / 128.0f, c / 128.0f);
    } else if (tid < 17408) {              // tIy4
        int i = tid - 15360; int p = i >> 6, rem = i & 63;
        int yg = rem >> 2, jy2 = rem & 3;
        int y0 = yg + 32 * jy2, y1 = y0 + 16;
        int j = (p + 48) % 65;
        float cp = (j == 0 || j == 64) ? 1.0f : 2.0f;
        int r0 = (j * y0) & 127, r1 = (j * y1) & 127;
        float s0, c0, s1, c1;
        sincospif(2.0f * (float)r0 / 128.0f, &s0, &c0);
        sincospif(2.0f * (float)r1 / 128.0f, &s1, &c1);
        g_tIy4[p * 64 + rem] = make_float4(cp * c0 / 128.0f, cp * c1 / 128.0f,
                                           -cp * s0 / 128.0f, -cp * s1 / 128.0f);
    }
}

// ================= K1: fused forward Y-DFT + X-DFT, one (b,i,t) plane per block =================
#define K1_SMEM (128*129*4 + 128*33*8)   // 99840 B

__global__ __launch_bounds__(256, 2) void k_fwd_xy(const float* __restrict__ x)
{
    extern __shared__ float sm[];
    float*  xs = sm;                        // [128][129]
    float2* ay = (float2*)(sm + 128 * 129); // [128][33]

    int plane = blockIdx.x;                 // (b*32+i)*64 + t
    int tid = threadIdx.x;

    const float4* xp = (const float4*)(x + (size_t)plane * 16384);
    #pragma unroll
    for (int k = 0; k < 16; k++) {
        int idx = tid + k * 256;
        float4 v = xp[idx];
        int row = idx >> 5, c4 = (idx & 31) << 2;
        float* d = xs + row * 129 + c4;
        d[0] = v.x; d[1] = v.y; d[2] = v.z; d[3] = v.w;
    }
    __syncthreads();

    // ---- Y-DFT: ay[x][p] = sum_y xs[x][y] * (c,s) — packed (re,im) accumulators ----
    {
        int pg = tid & 7, xg = tid >> 3;    // xg 0..31, pg 0..7
        const u64t* tFy = (const u64t*)g_tFy;
        u64t acc[4][4];
        #pragma unroll
        for (int a = 0; a < 4; a++)
            #pragma unroll
            for (int b = 0; b < 4; b++) acc[a][b] = 0ULL;

        for (int y = 0; y < 128; y++) {
            u64t xb[4];
            #pragma unroll
            for (int jx = 0; jx < 4; jx++) xb[jx] = bcast2(xs[(xg + 32 * jx) * 129 + y]);
            #pragma unroll
            for (int jp = 0; jp < 4; jp++) {
                u64t f = __ldg(&tFy[y * 32 + pg + 8 * jp]);
                #pragma unroll
                for (int jx = 0; jx < 4; jx++) fma2(acc[jx][jp], xb[jx], f);
            }
        }
        #pragma unroll
        for (int jx = 0; jx < 4; jx++)
            #pragma unroll
            for (int jp = 0; jp < 4; jp++)
                ay[(xg + 32 * jx) * 33 + pg + 8 * jp] = f2of(acc[jx][jp]);
    }
    __syncthreads();

    // ---- X-DFT: out[q][p] = sum_x tFx[q][x] * ay[x][p]; 2 p-cols/thread ----
    {
        int p2 = tid & 15, qg = tid >> 4;   // qg 0..15
        const ulonglong2* tFx = (const ulonglong2*)g_tFx4;
        u64t acc[2][2];                     // [jq][pcol]
        acc[0][0] = acc[0][1] = acc[1][0] = acc[1][1] = 0ULL;

        for (int xx = 0; xx < 128; xx++) {
            float2 av0 = ay[xx * 33 + p2];
            float2 av1 = ay[xx * 33 + p2 + 16];
            u64t b0x = bcast2(av0.x), b0y = bcast2(av0.y);
            u64t b1x = bcast2(av1.x), b1y = bcast2(av1.y);
            #pragma unroll
            for (int jq = 0; jq < 2; jq++) {
                ulonglong2 f = __ldg(&tFx[(qg + 16 * jq) * 128 + xx]);
                fma2(acc[jq][0], b0x, f.x); fma2(acc[jq][0], b0y, f.y);
                fma2(acc[jq][1], b1x, f.x); fma2(acc[jq][1], b1y, f.y);
            }
        }
        float2* o = g_B2 + (size_t)plane * 1024;
        #pragma unroll
        for (int jq = 0; jq < 2; jq++) {
            o[(qg + 16 * jq) * 32 + p2]      = f2of(acc[jq][0]);
            o[(qg + 16 * jq) * 32 + p2 + 16] = f2of(acc[jq][1]);
        }
    }
}

// ================= K2: forward time DFT (64 -> 32 freqs), packed =================
__global__ __launch_bounds__(256) void k_fwd_t()
{
    __shared__ ulonglong2 sFt[2048];        // [tf][t] (c,s),(-s,c)  32 KB
    int tid = threadIdx.x;
    const ulonglong2* gFt = (const ulonglong2*)g_tFt4;
    #pragma unroll
    for (int k = 0; k < 8; k++) sFt[tid + k * 256] = gFt[tid + k * 256];
    __syncthreads();

    int blk = blockIdx.x;                   // 256 blocks
    int bi  = blk >> 2;
    int qp  = ((blk & 3) << 8) + tid;

    const float2* src = g_B2 + (size_t)bi * 65536 + qp;
    u64t acc[32];
    #pragma unroll
    for (int tf = 0; tf < 32; tf++) acc[tf] = 0ULL;

    for (int t = 0; t < 64; t++) {
        float2 v = __ldg(&src[(size_t)t * 1024]);
        u64t bx = bcast2(v.x), by = bcast2(v.y);
        #pragma unroll
        for (int tf = 0; tf < 32; tf++) {
            ulonglong2 f = sFt[tf * 64 + t];
            fma2(acc[tf], bx, f.x); fma2(acc[tf], by, f.y);
        }
    }
    float2* dst = g_C + (size_t)bi * 32768 + qp;
    #pragma unroll
    for (int tf = 0; tf < 32; tf++) dst[(size_t)tf * 1024] = f2of(acc[tf]);
}

// ================= K3a: mode mix; both batches share weight reads in-warp =================
// grid = 32(o) x 2(t-half) x 8(qp chunks of 128), 256 threads: b = tid&1, qp = chunk + tid/2
__global__ __launch_bounds__(256) void k_mix(const float* __restrict__ Wr,
                                             const float* __restrict__ Wi)
{
    int bx = blockIdx.x;
    int qc = bx & 7, th = (bx >> 3) & 1, o = bx >> 4;
    int tid = threadIdx.x;
    int b = tid & 1;
    int qp = qc * 128 + (tid >> 1);

    float2 D[16];
    #pragma unroll
    for (int k = 0; k < 16; k++) D[k] = make_float2(0.f, 0.f);

    const float2* Cp = g_C + ((size_t)(b * 32 + o) * 32) * 1024 + qp;
    for (int tau = 0; tau < 32; tau++) {
        float2 c = __ldg(&Cp[(size_t)tau * 1024]);
        size_t wb = ((size_t)((tau * 32 + o) * 32) + th * 16) * 1024 + qp;
        #pragma unroll
        for (int k = 0; k < 16; k++) {
            float a  = __ldg(Wr + wb + (size_t)k * 1024);
            float w  = __ldg(Wi + wb + (size_t)k * 1024);
            D[k].x = fmaf(c.x, a, fmaf(-c.y, w, D[k].x));
            D[k].y = fmaf(c.x, w, fmaf( c.y, a, D[k].y));
        }
    }
    float2* Dp = g_D + ((size_t)((b * 32 + o) * 32) + th * 16) * 1024 + qp;
    #pragma unroll
    for (int k = 0; k < 16; k++) Dp[(size_t)k * 1024] = D[k];
}

// ================= K3b: inverse time DFT 32 -> 64 with tau/tau+32 parity trick =================
__global__ __launch_bounds__(256) void k_inv_t()
{
    __shared__ float2 sIt[1024];            // [t2<32][t<32]
    int tid = threadIdx.x;
    #pragma unroll
    for (int k = 0; k < 4; k++) sIt[tid + k * 256] = g_tIt2[tid + k * 256];
    __syncthreads();

    int bo = blockIdx.x >> 2;
    int qp = ((blockIdx.x & 3) << 8) + tid;

    const float2* Dp = g_D + (size_t)bo * 32768 + qp;
    float2 Dt[32];
    #pragma unroll
    for (int t = 0; t < 32; t++) Dt[t] = __ldg(&Dp[(size_t)t * 1024]);

    float2* Ep = g_E + (size_t)bo * 65536 + qp;
    for (int t2 = 0; t2 < 32; t2++) {
        float2 aE = make_float2(0.f, 0.f), aO = make_float2(0.f, 0.f);
        #pragma unroll
        for (int h = 0; h < 16; h++) {
            float2 fe = sIt[t2 * 32 + 2 * h];
            float2 fo = sIt[t2 * 32 + 2 * h + 1];
            float2 de = Dt[2 * h], dd = Dt[2 * h + 1];
            aE.x = fmaf(de.x, fe.x, fmaf(-de.y, fe.y, aE.x));
            aE.y = fmaf(de.x, fe.y, fmaf( de.y, fe.x, aE.y));
            aO.x = fmaf(dd.x, fo.x, fmaf(-dd.y, fo.y, aO.x));
            aO.y = fmaf(dd.x, fo.y, fmaf( dd.y, fo.x, aO.y));
        }
        Ep[(size_t)t2 * 1024]        = make_float2(aE.x + aO.x, aE.y + aO.y);
        Ep[(size_t)(t2 + 32) * 1024] = make_float2(aE.x - aO.x, aE.y - aO.y);
    }
}

// ================= K4: fused inverse X-DFT + Hermitian c2r over Y, one (b,o,tau) plane =================
#define K4_SMEM (32*33*8 + 128*33*8)   // 42240 B

__global__ __launch_bounds__(256, 2) void k_inv_xy(float* __restrict__ out)
{
    extern __shared__ float smraw[];
    float2* es = (float2*)smraw;        // [32][33]
    float2* f2 = es + 32 * 33;          // [128][33]

    int plane = blockIdx.x;             // (b*32+o)*64 + tau
    int tid = threadIdx.x;

    const float2* Ep = g_E + (size_t)plane * 1024;
    #pragma unroll
    for (int k = 0; k < 4; k++) {
        int idx = tid + k * 256;
        float2 v = __ldg(&Ep[idx]);
        es[(idx >> 5) * 33 + (idx & 31)] = v;
    }
    __syncthreads();

    // ---- inverse X: f2[x][p] = sum_q es[q][p] * tIx[x][q]; 2 p-cols/thread ----
    {
        int p2 = tid & 15, xg = tid >> 4;   // xg 0..15
        const ulonglong2* tIx = (const ulonglong2*)g_tIx4;
        u64t acc[8][2];
        #pragma unroll
        for (int j = 0; j < 8; j++) { acc[j][0] = 0ULL; acc[j][1] = 0ULL; }

        for (int q = 0; q < 32; q++) {
            float2 av0 = es[q * 33 + p2];
            float2 av1 = es[q * 33 + p2 + 16];
            u64t b0x = bcast2(av0.x), b0y = bcast2(av0.y);
            u64t b1x = bcast2(av1.x), b1y = bcast2(av1.y);
            #pragma unroll
            for (int j = 0; j < 8; j++) {
                ulonglong2 f = __ldg(&tIx[(xg + 16 * j) * 32 + q]);
                fma2(acc[j][0], b0x, f.x); fma2(acc[j][0], b0y, f.y);
                fma2(acc[j][1], b1x, f.x); fma2(acc[j][1], b1y, f.y);
            }
        }
        #pragma unroll
        for (int j = 0; j < 8; j++) {
            f2[(xg + 16 * j) * 33 + p2]      = f2of(acc[j][0]);
            f2[(xg + 16 * j) * 33 + p2 + 16] = f2of(acc[j][1]);
        }
    }
    __syncthreads();

    // ---- inverse Y (c2r): out[x][y] = sum_p Re*a + Im*b, y-pairs packed ----
    {
        int yg = tid & 15, xg = tid >> 4;   // xg 0..15
        const ulonglong2* tIy = (const ulonglong2*)g_tIy4;
        u64t acc[8][4];                     // [jx][jy2], packs (y0, y1=y0+16)
        #pragma unroll
        for (int jx = 0; jx < 8; jx++)
            #pragma unroll
            for (int j2 = 0; j2 < 4; j2++) acc[jx][j2] = 0ULL;

        for (int p = 0; p < 32; p++) {
            u64t fxb[8], fyb[8];
            #pragma unroll
            for (int jx = 0; jx < 8; jx++) {
                float2 fv = f2[(xg + 16 * jx) * 33 + p];
                fxb[jx] = bcast2(fv.x); fyb[jx] = bcast2(fv.y);
            }
            #pragma unroll
            for (int j2 = 0; j2 < 4; j2++) {
                ulonglong2 ab = __ldg(&tIy[p * 64 + yg * 4 + j2]);  // (a0,a1),(b0,b1)
                #pragma unroll
                for (int jx = 0; jx < 8; jx++) {
                    fma2(acc[jx][j2], fxb[jx], ab.x);
                    fma2(acc[jx][j2], fyb[jx], ab.y);
                }
            }
        }
        float* op = out + (size_t)plane * 16384;
        #pragma unroll
        for (int jx = 0; jx < 8; jx++)
            #pragma unroll
            for (int j2 = 0; j2 < 4; j2++) {
                float2 r = f2of(acc[jx][j2]);
                int xrow = (xg + 16 * jx) * 128;
                op[xrow + yg + 32 * j2]      = r.x;
                op[xrow + yg + 32 * j2 + 16] = r.y;
            }
    }
}

// ---------------- launcher ----------------
extern "C" void kernel_launch(void* const* d_in, const int* in_sizes, int n_in,
                              void* d_out, int out_size)
{
    const float* x  = (const float*)d_in[0];
    const float* wr = (const float*)d_in[1];
    const float* wi = (const float*)d_in[2];
    float* out = (float*)d_out;

    cudaFuncSetAttribute(k_fwd_xy, cudaFuncAttributeMaxDynamicSharedMemorySize, K1_SMEM);

    k_init_tables<<<80, 256>>>();
    k_fwd_xy<<<BB * CI * TT, 256, K1_SMEM>>>(x);
    k_fwd_t<<<256, 256>>>();
    k_mix<<<512, 256>>>(wr, wi);
    k_inv_t<<<256, 256>>>();
    k_inv_xy<<<BB * CO * TT, 256, K4_SMEM>>>(out);
}

// round 17
// speedup vs baseline: 1.6071x; 1.6071x over previous
#include <cuda_runtime.h>
#include <math.h>

// Problem constants
#define BB 2
#define CI 32
#define CO 32
#define TT 64
#define MT 32

typedef unsigned long long u64t;

// ---------- packed f32x2 helpers ----------
__device__ __forceinline__ u64t pack2(float lo, float hi) {
    u64t r; asm("mov.b64 %0, {%1, %2};" : "=l"(r) : "f"(lo), "f"(hi)); return r;
}
__device__ __forceinline__ u64t bcast2(float v) { return pack2(v, v); }
__device__ __forceinline__ void fma2(u64t& d, u64t a, u64t b) {
    asm("fma.rn.f32x2 %0, %1, %2, %3;" : "=l"(d) : "l"(a), "l"(b), "l"(d));
}
__device__ __forceinline__ float2 f2of(u64t v) {
    float lo, hi; asm("mov.b64 {%0, %1}, %2;" : "=f"(lo), "=f"(hi) : "l"(v));
    return make_float2(lo, hi);
}

// -------- scratch --------
__device__ float2 g_B2[BB*CI*TT*1024];   // (b,i,t,q,p)
__device__ float2 g_C [BB*CI*MT*1024];   // (b,i,tf,q,p)
__device__ float2 g_D [BB*CO*MT*1024];   // (b,o,t,q,p)
__device__ float2 g_E [BB*CO*TT*1024];   // (b,o,tau,q,p)

// -------- twiddle tables --------
__device__ float2 g_twY [65*32];  // [y][p]  (c, -s): c=cos(2pi j_in(p) y/128), s=sin, j_in=(p+49)%65
__device__ float4 g_csX [65*32];  // [x][q]  (c,c,s,s): theta=2pi kx(q) x/128, kx=(q+112)%128
__device__ float4 g_csIX[65*32];  // [x][q]  (c,c,s,s)/128 (inverse X)
__device__ float2 g_tab [32*65];  // [p][y]  (a,b): a=cp*cos(2pi j_out y/128)/128, b=-cp*sin/128, j_out=(p+48)%65
__device__ float4 g_tFt4[32*64];  // [tf][t] (c,s,-s,c): e^{-2pi i tf t/64}
__device__ float2 g_tIt2[32*32];  // [t2][t] (c,s)/64: e^{+2pi i t2 t/64}

__global__ void k_init_tables()
{
    int i = blockIdx.x * blockDim.x + threadIdx.x;
    if (i < 2080) {                                   // twY
        int y = i >> 5, p = i & 31;
        int j = (p + 49) % 65; int r = (j * y) & 127;
        float s, c; sincospif(2.0f * (float)r / 128.0f, &s, &c);
        g_twY[i] = make_float2(c, -s);
    } else if (i < 4160) {                            // csX
        int t = i - 2080; int xx = t >> 5, q = t & 31;
        int k = (q + 112) & 127; int r = (k * xx) & 127;
        float s, c; sincospif(2.0f * (float)r / 128.0f, &s, &c);
        g_csX[t] = make_float4(c, c, s, s);
    } else if (i < 6240) {                            // csIX
        int t = i - 4160; int xx = t >> 5, q = t & 31;
        int k = (q + 112) & 127; int r = (k * xx) & 127;
        float s, c; sincospif(2.0f * (float)r / 128.0f, &s, &c);
        g_csIX[t] = make_float4(c / 128.0f, c / 128.0f, s / 128.0f, s / 128.0f);
    } else if (i < 8320) {                            // tab
        int t = i - 6240; int p = t / 65, y = t % 65;
        int j = (p + 48) % 65;
        float cp = (j == 0 || j == 64) ? 1.0f : 2.0f;
        int r = (j * y) & 127;
        float s, c; sincospif(2.0f * (float)r / 128.0f, &s, &c);
        g_tab[t] = make_float2(cp * c / 128.0f, -cp * s / 128.0f);
    } else if (i < 10368) {                           // tFt4
        int t = i - 8320; int tf = t >> 6, tt = t & 63;
        int r = (tf * tt) & 63;
        float s, c; sincospif(-2.0f * (float)r / 64.0f, &s, &c);
        g_tFt4[t] = make_float4(c, s, -s, c);
    } else if (i < 11392) {                           // tIt2
        int t = i - 10368; int t2 = t >> 5, tt = t & 31;
        int r = (t2 * tt) & 63;
        float s, c; sincospif(2.0f * (float)r / 64.0f, &s, &c);
        g_tIt2[t] = make_float2(c / 64.0f, s / 64.0f);
    }
}

// ================= K1: forward Y-DFT + X-DFT with Hermitian pairing =================
// smem: region A [0, 67584): uv[128][66] float2, later reused for csX[65*32] ulonglong2 (33280B)
//       region B [67584, 101376): ay[128][33] float2
#define K1_SMEM (128*66*8 + 128*33*8)

__global__ __launch_bounds__(256, 2) void k_fwd_xy(const float* __restrict__ x)
{
    extern __shared__ float smraw[];
    float2* uv = (float2*)smraw;                    // [128][66]
    ulonglong2* csX = (ulonglong2*)smraw;           // overlays uv (phase 2)
    float2* ay = (float2*)(smraw + 128 * 66 * 2);   // [128][33]

    int plane = blockIdx.x;                         // (b*32+i)*64 + t
    int tid = threadIdx.x;

    // ---- load + y-butterfly: uv[r][y] = (x[y]+x[128-y], x[y]-x[128-y]) ----
    const float* xp = x + (size_t)plane * 16384;
    for (int i = tid; i < 8320; i += 256) {         // 128*65
        int r = i / 65, y = i - r * 65;
        float a = __ldg(xp + r * 128 + y);
        float u, v;
        if (y == 0 || y == 64) { u = a; v = 0.f; }
        else { float b = __ldg(xp + r * 128 + 128 - y); u = a + b; v = a - b; }
        uv[r * 66 + y] = make_float2(u, v);
    }
    __syncthreads();

    // ---- Y-main: ay[x][p] = (sum u*c, sum v*(-s)), y=0..64, 1 fma2/(x,p,y) ----
    {
        int pg = tid & 7, xg = tid >> 3;            // rows xg+32jx, bins pg+8jp
        const u64t* twY = (const u64t*)g_twY;
        u64t acc[4][4];
        #pragma unroll
        for (int a = 0; a < 4; a++)
            #pragma unroll
            for (int b = 0; b < 4; b++) acc[a][b] = 0ULL;

        for (int y = 0; y <= 64; y++) {
            u64t uvr[4];
            #pragma unroll
            for (int jx = 0; jx < 4; jx++)
                uvr[jx] = *(const u64t*)&uv[(xg + 32 * jx) * 66 + y];
            #pragma unroll
            for (int jp = 0; jp < 4; jp++) {
                u64t f = __ldg(&twY[y * 32 + pg + 8 * jp]);
                #pragma unroll
                for (int jx = 0; jx < 4; jx++) fma2(acc[jx][jp], uvr[jx], f);
            }
        }
        #pragma unroll
        for (int jx = 0; jx < 4; jx++)
            #pragma unroll
            for (int jp = 0; jp < 4; jp++)
                ay[(xg + 32 * jx) * 33 + pg + 8 * jp] = f2of(acc[jx][jp]);
    }
    __syncthreads();

    // ---- x-butterfly in ay (U at [x], V at [128-x]) + load csX into region A ----
    for (int i = tid; i < 2016; i += 256) {         // 63*32
        int xx = (i >> 5) + 1, p = i & 31;
        float2 a = ay[xx * 33 + p], b = ay[(128 - xx) * 33 + p];
        ay[xx * 33 + p]         = make_float2(a.x + b.x, a.y + b.y);
        ay[(128 - xx) * 33 + p] = make_float2(a.x - b.x, a.y - b.y);
    }
    for (int i = tid; i < 2080; i += 256) {
        float4 v = __ldg(&g_csX[i]);
        csX[i] = *(const ulonglong2*)&v;
    }
    __syncthreads();

    // ---- X-main: B[q][p] = sum_{x=0..64} U*c - iV*s ----
    {
        int p2 = tid & 15, qg = tid >> 4;           // q = qg+16jq, p = p2, p2+16
        u64t acc[2][2];
        acc[0][0] = acc[0][1] = acc[1][0] = acc[1][1] = 0ULL;

        for (int xx = 0; xx <= 64; xx++) {
            int xm = (128 - xx) & 127;
            u64t u0 = *(const u64t*)&ay[xx * 33 + p2];
            u64t u1 = *(const u64t*)&ay[xx * 33 + p2 + 16];
            float2 V0 = ay[xm * 33 + p2];
            float2 V1 = ay[xm * 33 + p2 + 16];
            u64t vs0 = pack2(V0.y, -V0.x);
            u64t vs1 = pack2(V1.y, -V1.x);
            #pragma unroll
            for (int jq = 0; jq < 2; jq++) {
                ulonglong2 cs = csX[xx * 32 + qg + 16 * jq];
                fma2(acc[jq][0], u0, cs.x); fma2(acc[jq][0], vs0, cs.y);
                fma2(acc[jq][1], u1, cs.x); fma2(acc[jq][1], vs1, cs.y);
            }
        }
        float2* o = g_B2 + (size_t)plane * 1024;
        #pragma unroll
        for (int jq = 0; jq < 2; jq++) {
            o[(qg + 16 * jq) * 32 + p2]      = f2of(acc[jq][0]);
            o[(qg + 16 * jq) * 32 + p2 + 16] = f2of(acc[jq][1]);
        }
    }
}

// ================= K2: forward time DFT (64 -> 32) =================
__global__ __launch_bounds__(256) void k_fwd_t()
{
    __shared__ ulonglong2 sFt[2048];
    int tid = threadIdx.x;
    const ulonglong2* gFt = (const ulonglong2*)g_tFt4;
    #pragma unroll
    for (int k = 0; k < 8; k++) sFt[tid + k * 256] = gFt[tid + k * 256];
    __syncthreads();

    int blk = blockIdx.x;
    int bi  = blk >> 2;
    int qp  = ((blk & 3) << 8) + tid;

    const float2* src = g_B2 + (size_t)bi * 65536 + qp;
    u64t acc[32];
    #pragma unroll
    for (int tf = 0; tf < 32; tf++) acc[tf] = 0ULL;

    for (int t = 0; t < 64; t++) {
        float2 v = __ldg(&src[(size_t)t * 1024]);
        u64t bx = bcast2(v.x), by = bcast2(v.y);
        #pragma unroll
        for (int tf = 0; tf < 32; tf++) {
            ulonglong2 f = sFt[tf * 64 + t];
            fma2(acc[tf], bx, f.x); fma2(acc[tf], by, f.y);
        }
    }
    float2* dst = g_C + (size_t)bi * 32768 + qp;
    #pragma unroll
    for (int tf = 0; tf < 32; tf++) dst[(size_t)tf * 1024] = f2of(acc[tf]);
}

// ================= K3a: mode mix =================
__global__ __launch_bounds__(256) void k_mix(const float* __restrict__ Wr,
                                             const float* __restrict__ Wi)
{
    int bx = blockIdx.x;
    int qc = bx & 7, th = (bx >> 3) & 1, o = bx >> 4;
    int tid = threadIdx.x;
    int b = tid & 1;
    int qp = qc * 128 + (tid >> 1);

    float2 D[16];
    #pragma unroll
    for (int k = 0; k < 16; k++) D[k] = make_float2(0.f, 0.f);

    const float2* Cp = g_C + ((size_t)(b * 32 + o) * 32) * 1024 + qp;
    for (int tau = 0; tau < 32; tau++) {
        float2 c = __ldg(&Cp[(size_t)tau * 1024]);
        size_t wb = ((size_t)((tau * 32 + o) * 32) + th * 16) * 1024 + qp;
        #pragma unroll
        for (int k = 0; k < 16; k++) {
            float a = __ldg(Wr + wb + (size_t)k * 1024);
            float w = __ldg(Wi + wb + (size_t)k * 1024);
            D[k].x = fmaf(c.x, a, fmaf(-c.y, w, D[k].x));
            D[k].y = fmaf(c.x, w, fmaf( c.y, a, D[k].y));
        }
    }
    float2* Dp = g_D + ((size_t)((b * 32 + o) * 32) + th * 16) * 1024 + qp;
    #pragma unroll
    for (int k = 0; k < 16; k++) Dp[(size_t)k * 1024] = D[k];
}

// ================= K3b: inverse time DFT (parity trick) =================
__global__ __launch_bounds__(256) void k_inv_t()
{
    __shared__ float2 sIt[1024];
    int tid = threadIdx.x;
    #pragma unroll
    for (int k = 0; k < 4; k++) sIt[tid + k * 256] = g_tIt2[tid + k * 256];
    __syncthreads();

    int bo = blockIdx.x >> 2;
    int qp = ((blockIdx.x & 3) << 8) + tid;

    const float2* Dp = g_D + (size_t)bo * 32768 + qp;
    float2 Dt[32];
    #pragma unroll
    for (int t = 0; t < 32; t++) Dt[t] = __ldg(&Dp[(size_t)t * 1024]);

    float2* Ep = g_E + (size_t)bo * 65536 + qp;
    for (int t2 = 0; t2 < 32; t2++) {
        float2 aE = make_float2(0.f, 0.f), aO = make_float2(0.f, 0.f);
        #pragma unroll
        for (int h = 0; h < 16; h++) {
            float2 fe = sIt[t2 * 32 + 2 * h];
            float2 fo = sIt[t2 * 32 + 2 * h + 1];
            float2 de = Dt[2 * h], dd = Dt[2 * h + 1];
            aE.x = fmaf(de.x, fe.x, fmaf(-de.y, fe.y, aE.x));
            aE.y = fmaf(de.x, fe.y, fmaf( de.y, fe.x, aE.y));
            aO.x = fmaf(dd.x, fo.x, fmaf(-dd.y, fo.y, aO.x));
            aO.y = fmaf(dd.x, fo.y, fmaf( dd.y, fo.x, aO.y));
        }
        Ep[(size_t)t2 * 1024]        = make_float2(aE.x + aO.x, aE.y + aO.y);
        Ep[(size_t)(t2 + 32) * 1024] = make_float2(aE.x - aO.x, aE.y - aO.y);
    }
}

// ================= K4: inverse X + c2r, both with output pairing =================
// smem: es[32][33] f2 (8448) | f2buf[128][33] f2 (33792) | csIX 2080 ul2 (33280) | tab 2080 u64 (16640)
#define K4_ES    0
#define K4_F2    8448
#define K4_CSIX  42240
#define K4_TAB   75520
#define K4_SMEM  92160

__global__ __launch_bounds__(256, 2) void k_inv_xy(float* __restrict__ out)
{
    extern __shared__ char smk4[];
    float2*     es   = (float2*)(smk4 + K4_ES);      // [32][33]
    float2*     f2b  = (float2*)(smk4 + K4_F2);      // [128][33]
    ulonglong2* csIX = (ulonglong2*)(smk4 + K4_CSIX);
    u64t*       tab  = (u64t*)(smk4 + K4_TAB);

    int plane = blockIdx.x;                          // (b*32+o)*64 + tau
    int tid = threadIdx.x;

    const float2* Ep = g_E + (size_t)plane * 1024;
    #pragma unroll
    for (int k = 0; k < 4; k++) {
        int idx = tid + k * 256;
        float2 v = __ldg(&Ep[idx]);
        es[(idx >> 5) * 33 + (idx & 31)] = v;
    }
    for (int i = tid; i < 2080; i += 256) {
        float4 v = __ldg(&g_csIX[i]);
        csIX[i] = *(const ulonglong2*)&v;
        float2 t = __ldg(&g_tab[i]);
        tab[i] = *(const u64t*)&t;
    }
    __syncthreads();

    // ---- phase 1: inverse X with output pairing: F[x]=P+iQ, F[128-x]=P-iQ ----
    {
        int p2 = tid & 15, xg = tid >> 4;            // x slots: xg+16j (j<4), j=4 -> x=64 (dup)
        u64t P[5][2], Q[5][2];
        #pragma unroll
        for (int j = 0; j < 5; j++) { P[j][0]=P[j][1]=Q[j][0]=Q[j][1]=0ULL; }

        for (int q = 0; q < 32; q++) {
            u64t e0 = *(const u64t*)&es[q * 33 + p2];
            u64t e1 = *(const u64t*)&es[q * 33 + p2 + 16];
            #pragma unroll
            for (int j = 0; j < 5; j++) {
                int xx = (j < 4) ? (xg + 16 * j) : 64;
                ulonglong2 cs = csIX[xx * 32 + q];
                fma2(P[j][0], e0, cs.x); fma2(Q[j][0], e0, cs.y);
                fma2(P[j][1], e1, cs.x); fma2(Q[j][1], e1, cs.y);
            }
        }
        #pragma unroll
        for (int j = 0; j < 5; j++) {
            int xx = (j < 4) ? (xg + 16 * j) : 64;
            int xo = (128 - xx) & 127;
            #pragma unroll
            for (int col = 0; col < 2; col++) {
                int pp = p2 + 16 * col;
                float2 p = f2of(P[j][col]), q_ = f2of(Q[j][col]);
                f2b[xx * 33 + pp] = make_float2(p.x - q_.y, p.y + q_.x);
                f2b[xo * 33 + pp] = make_float2(p.x + q_.y, p.y - q_.x);
            }
        }
    }
    __syncthreads();

    // ---- phase 2: c2r with output pairing; acc=(C,S) += (Fr,Fi)*(a,b); out=C+-S ----
    {
        int yg = tid & 15, xgr = tid >> 4;
        float* op = out + (size_t)plane * 16384;
        #pragma unroll
        for (int pass = 0; pass < 2; pass++) {
            u64t acc[4][5];
            #pragma unroll
            for (int jx = 0; jx < 4; jx++)
                #pragma unroll
                for (int j = 0; j < 5; j++) acc[jx][j] = 0ULL;

            for (int p = 0; p < 32; p++) {
                u64t tb[5];
                #pragma unroll
                for (int j = 0; j < 5; j++) {
                    int y = (j < 4) ? (yg + 16 * j) : 64;
                    tb[j] = tab[p * 65 + y];
                }
                #pragma unroll
                for (int jx = 0; jx < 4; jx++) {
                    u64t F = *(const u64t*)&f2b[(xgr + 16 * jx + 64 * pass) * 33 + p];
                    #pragma unroll
                    for (int j = 0; j < 5; j++) fma2(acc[jx][j], F, tb[j]);
                }
            }
            #pragma unroll
            for (int jx = 0; jx < 4; jx++) {
                int row = (xgr + 16 * jx + 64 * pass) * 128;
                #pragma unroll
                for (int j = 0; j < 5; j++) {
                    int y = (j < 4) ? (yg + 16 * j) : 64;
                    int ym = (128 - y) & 127;
                    float2 cs_ = f2of(acc[jx][j]);       // (C, S)
                    op[row + y]  = cs_.x + cs_.y;
                    op[row + ym] = cs_.x - cs_.y;
                }
            }
        }
    }
}

// ---------------- launcher ----------------
extern "C" void kernel_launch(void* const* d_in, const int* in_sizes, int n_in,
                              void* d_out, int out_size)
{
    const float* x  = (const float*)d_in[0];
    const float* wr = (const float*)d_in[1];
    const float* wi = (const float*)d_in[2];
    float* out = (float*)d_out;

    cudaFuncSetAttribute(k_fwd_xy, cudaFuncAttributeMaxDynamicSharedMemorySize, K1_SMEM);
    cudaFuncSetAttribute(k_inv_xy, cudaFuncAttributeMaxDynamicSharedMemorySize, K4_SMEM);

    k_init_tables<<<45, 256>>>();
    k_fwd_xy<<<BB * CI * TT, 256, K1_SMEM>>>(x);
    k_fwd_t<<<256, 256>>>();
    k_mix<<<512, 256>>>(wr, wi);
    k_inv_t<<<256, 256>>>();
    k_inv_xy<<<BB * CO * TT, 256, K4_SMEM>>>(out);
}